// round 9
// baseline (speedup 1.0000x reference)
#include <cuda_runtime.h>
#include <math.h>

// Chamfer loss, B=4, C=3, Np=Ng=8192. R9:
//  R7 scalar core + AXIS SWAP: tx (lane bits 0-3) indexes p, ty indexes g.
//  => per-stage column-min reduce is INTRA-WARP (4 shfl rounds), no cbuf,
//     no reduce barrier/tail; row-min reduce crosses warps but only ONCE.
//  Evidence: R7 profile issue=67.9% with per-stage smem reduce tail; R8
//  disproved f32x2 (FFMA2 = 2 fma slots on sm_103a).
// Per pair: e = fma(-2px,gx, fma(-2py,gy, fma(-2pz,gz, g2)));  d2 = e + p2
// sqrt only on final mins (monotone). Col-min via int atomicMin on positive
// clamped float bits (order-independent => deterministic).

#define BATCH   4
#define NPT     8192
#define TPQ     128                      // predict points per block
#define TGQ     128                      // gt points per stage
#define NSTAGES (NPT / TGQ)              // 64
#define NTH     256                      // 16 (p=tx) x 16 (g=ty)
#define EPSF    1e-12f
#define FLTMAXI 0x7f7fffff

__device__ int   g_colmin[BATCH * NPT];
__device__ float g_rowsum[BATCH * (NPT / TPQ)];

#define INIT_CHUNK ((BATCH * NPT) / 3 + 1)
__global__ void init_kernel(int base) {
    int i = base + blockIdx.x * blockDim.x + threadIdx.x;
    if (i < BATCH * NPT) g_colmin[i] = FLTMAXI;
}

__global__ __launch_bounds__(NTH, 3)
void chamfer_main(const float* __restrict__ P, const float* __restrict__ G) {
    const int b     = blockIdx.y;
    const int pbase = blockIdx.x * TPQ;
    const float* Pb = P + (size_t)b * 3 * NPT;
    const float* Gb = G + (size_t)b * 3 * NPT;
    const int tid = threadIdx.x;
    const int tx  = tid & 15;        // p direction (low lane bits -> intra-warp g reduce)
    const int ty  = tid >> 4;        // g direction

    __shared__ float4 sp[TPQ];
    __shared__ float4 sg[2][TGQ];               // double buffer
    __shared__ float  rbuf[16][TPQ + 1];        // one-time row reduce, padded

    // ---- prologue: prefetch stage-0 gt, load & transform p tile ----
    float rx = 0.f, ry = 0.f, rz = 0.f;
    if (tid < TGQ) {
        rx = Gb[tid];
        ry = Gb[NPT + tid];
        rz = Gb[2 * NPT + tid];
    }
    for (int i = tid; i < TPQ; i += NTH) {
        float px = Pb[pbase + i];
        float py = Pb[NPT + pbase + i];
        float pz = Pb[2 * NPT + pbase + i];
        sp[i] = make_float4(-2.f * px, -2.f * py, -2.f * pz,
                            px * px + py * py + pz * pz);
    }
    if (tid < TGQ)
        sg[0][tid] = make_float4(rx, ry, rz, rx * rx + ry * ry + rz * rz);
    __syncthreads();

    // p rows strided by 16: row = ii*16 + tx  (conflict-free LDS.128)
    float pa[8], pb_[8], pc[8], pp2[8], rowmin[8];
#pragma unroll
    for (int ii = 0; ii < 8; ii++) {
        float4 v = sp[ii * 16 + tx];
        pa[ii] = v.x; pb_[ii] = v.y; pc[ii] = v.z; pp2[ii] = v.w;
        rowmin[ii] = 3.4e38f;     // tracks e; p2 added once at the end
    }

    for (int s = 0; s < NSTAGES; s++) {
        const int cur = s & 1, nxt = cur ^ 1;

        // issue next-stage gmem loads now; latency hidden under compute
        if (s + 1 < NSTAGES && tid < TGQ) {
            int g = (s + 1) * TGQ + tid;
            rx = Gb[g]; ry = Gb[NPT + g]; rz = Gb[2 * NPT + g];
        }

        // two g-passes of 64 columns each (RG=4); g col = h*64 + jj*16 + ty
#pragma unroll
        for (int h = 0; h < 2; h++) {
            float gx[4], gy[4], gz[4], g2[4], colmin[4];
#pragma unroll
            for (int jj = 0; jj < 4; jj++) {
                float4 v = sg[cur][h * 64 + jj * 16 + ty];   // broadcast read
                gx[jj] = v.x; gy[jj] = v.y; gz[jj] = v.z; g2[jj] = v.w;
                colmin[jj] = 3.4e38f;
            }

#pragma unroll
            for (int ii = 0; ii < 8; ii++) {
#pragma unroll
                for (int jj = 0; jj < 4; jj++) {
                    float e = fmaf(pc[ii], gz[jj], g2[jj]);
                    e = fmaf(pb_[ii], gy[jj], e);
                    e = fmaf(pa[ii], gx[jj], e);
                    rowmin[ii] = fminf(rowmin[ii], e);
                    colmin[jj] = fminf(colmin[jj], e + pp2[ii]);
                }
            }

            // intra-warp col reduce across tx (lane bits 0-3), then flush
#pragma unroll
            for (int jj = 0; jj < 4; jj++) {
                float m = colmin[jj];
#pragma unroll
                for (int off = 1; off < 16; off <<= 1)
                    m = fminf(m, __shfl_xor_sync(0xffffffffu, m, off));
                if (tx == 0) {
                    m = fmaxf(m, EPSF);   // clamp (ref); positive => int order ok
                    atomicMin(&g_colmin[b * NPT + s * TGQ + h * 64 + jj * 16 + ty],
                              __float_as_int(m));
                }
            }
        }

        // stage s+1 gt chunk -> other smem buffer (prefetch regs landed)
        if (s + 1 < NSTAGES && tid < TGQ)
            sg[nxt][tid] = make_float4(rx, ry, rz, rx * rx + ry * ry + rz * rz);

        __syncthreads();   // the ONLY barrier per stage
    }

    // ---- one-time row-min reduce across ty (cross-warp, via smem) ----
#pragma unroll
    for (int ii = 0; ii < 8; ii++)
        rbuf[ty][ii * 16 + tx] = rowmin[ii];
    __syncthreads();

    float rsum = 0.f;
    if (tid < TPQ) {
        float m = rbuf[0][tid];
#pragma unroll
        for (int t = 1; t < 16; t++) m = fminf(m, rbuf[t][tid]);
        float p2 = sp[tid].w;
        rsum = sqrtf(fmaxf(m + p2, EPSF));
    }

    __shared__ float sred[NTH];
    sred[tid] = rsum;
    __syncthreads();
    for (int st = NTH / 2; st > 0; st >>= 1) {
        if (tid < st) sred[tid] += sred[tid + st];
        __syncthreads();
    }
    if (tid == 0)
        g_rowsum[b * gridDim.x + blockIdx.x] = sred[0];
}

__global__ void finalize_kernel(float* out, int nblocks) {
    __shared__ float sred[256];
    const int tid = threadIdx.x;
    float s = 0.f;
    for (int i = tid; i < BATCH * NPT; i += 256)
        s += sqrtf(__int_as_float(g_colmin[i]));   // already clamped >= EPS
    for (int i = tid; i < nblocks; i += 256)
        s += g_rowsum[i];
    sred[tid] = s;
    __syncthreads();
    for (int st = 128; st > 0; st >>= 1) {
        if (tid < st) sred[tid] += sred[tid + st];
        __syncthreads();
    }
    if (tid == 0)
        out[0] = sred[0] / (float)(BATCH * 2 * NPT);   // denom = B*(Np+Ng)
}

extern "C" void kernel_launch(void* const* d_in, const int* in_sizes, int n_in,
                              void* d_out, int out_size) {
    const float* P = (const float*)d_in[0];
    const float* G = (const float*)d_in[1];

    // three init launches so chamfer_main is kernel-launch index 3 (ncu target)
    init_kernel<<<(INIT_CHUNK + 255) / 256, 256>>>(0);
    init_kernel<<<(INIT_CHUNK + 255) / 256, 256>>>(INIT_CHUNK);
    init_kernel<<<(INIT_CHUNK + 255) / 256, 256>>>(2 * INIT_CHUNK);

    dim3 grid(NPT / TPQ, BATCH);             // 64 x 4 = 256 blocks
    chamfer_main<<<grid, NTH>>>(P, G);

    finalize_kernel<<<1, 256>>>((float*)d_out, BATCH * (NPT / TPQ));
}

// round 10
// speedup vs baseline: 1.1844x; 1.1844x over previous
#include <cuda_runtime.h>
#include <math.h>

// Chamfer loss, B=4, C=3, Np=Ng=8192. R10 = R7 core + single-launch design:
//  - col-min kept as atomicMax of (0x7f7fffff - bits): zero-init == FLT_MAX,
//    so no init kernel is needed (device globals are .bss zero).
//  - row partials accumulated in a fixed-point u64 (integer adds commute =>
//    deterministic, no float-atomic ordering issues).
//  - last block (ticket == gridSize-1 after threadfence) performs the
//    finalize (sqrt + sum of col mins, add row total, write out) and RESETS
//    all globals to zero so every graph replay sees identical start state.
//  Evidence: per-launch overhead ~3.5us (pad_kernel measurement); e2e-main
//  gap was ~36us across R6-R9. R7 main loop (77.0us) kept verbatim.

#define BATCH   4
#define NPT     8192
#define TPQ     128                      // predict points per block
#define TGQ     128                      // gt points per stage
#define NSTAGES (NPT / TGQ)              // 64
#define NTH     256                      // 16 (g=tx) x 16 (p=ty)
#define NBLOCKS (BATCH * (NPT / TPQ))    // 256
#define EPSF    1e-12f
#define FPSCALE 4294967296.0             // 2^32 fixed point

__device__ unsigned int       g_colmax[BATCH * NPT];   // complement-encoded mins (0 = FLT_MAX)
__device__ unsigned long long g_rowacc;                // fixed-point row-sum accumulator
__device__ unsigned int       g_done;                  // completed-block counter

__global__ __launch_bounds__(NTH, 3)
void chamfer_main(const float* __restrict__ P, const float* __restrict__ G,
                  float* __restrict__ out) {
    const int b     = blockIdx.y;
    const int pbase = blockIdx.x * TPQ;
    const float* Pb = P + (size_t)b * 3 * NPT;
    const float* Gb = G + (size_t)b * 3 * NPT;
    const int tid = threadIdx.x;
    const int tx  = tid & 15;        // g direction
    const int ty  = tid >> 4;        // p direction

    __shared__ float4 sp[TPQ];
    __shared__ float4 sg[2][TGQ];               // double buffer
    __shared__ float  cbuf[2][16][TGQ + 1];     // double buffer, padded
    __shared__ float  sred[NTH];
    __shared__ unsigned int ticket;

    // ---- prologue: prefetch stage-0 gt, load & transform p tile ----
    float rx = 0.f, ry = 0.f, rz = 0.f;
    if (tid < TGQ) {
        rx = Gb[tid];
        ry = Gb[NPT + tid];
        rz = Gb[2 * NPT + tid];
    }
    for (int i = tid; i < TPQ; i += NTH) {
        float px = Pb[pbase + i];
        float py = Pb[NPT + pbase + i];
        float pz = Pb[2 * NPT + pbase + i];
        sp[i] = make_float4(-2.f * px, -2.f * py, -2.f * pz,
                            px * px + py * py + pz * pz);
    }
    if (tid < TGQ)
        sg[0][tid] = make_float4(rx, ry, rz, rx * rx + ry * ry + rz * rz);
    __syncthreads();

    float pa[8], pb_[8], pc[8], pp2[8], rowmin[8];
#pragma unroll
    for (int ii = 0; ii < 8; ii++) {
        float4 v = sp[ty * 8 + ii];
        pa[ii] = v.x; pb_[ii] = v.y; pc[ii] = v.z; pp2[ii] = v.w;
        rowmin[ii] = 3.4e38f;
    }

    for (int s = 0; s < NSTAGES; s++) {
        const int cur = s & 1, nxt = cur ^ 1;

        // issue next-stage gmem loads now; latency hidden under compute
        if (s + 1 < NSTAGES && tid < TGQ) {
            int g = (s + 1) * TGQ + tid;
            rx = Gb[g]; ry = Gb[NPT + g]; rz = Gb[2 * NPT + g];
        }

        // two g-passes of 64 columns each (RG=4) to keep registers small
#pragma unroll
        for (int h = 0; h < 2; h++) {
            float gx[4], gy[4], gz[4], g2[4], colmin[4];
#pragma unroll
            for (int jj = 0; jj < 4; jj++) {
                float4 v = sg[cur][h * 64 + jj * 16 + tx];
                gx[jj] = v.x; gy[jj] = v.y; gz[jj] = v.z; g2[jj] = v.w;
                colmin[jj] = 3.4e38f;
            }

#pragma unroll
            for (int ii = 0; ii < 8; ii++) {
#pragma unroll
                for (int jj = 0; jj < 4; jj++) {
                    float e = fmaf(pc[ii], gz[jj], g2[jj]);
                    e = fmaf(pb_[ii], gy[jj], e);
                    e = fmaf(pa[ii], gx[jj], e);
                    rowmin[ii] = fminf(rowmin[ii], e);
                    colmin[jj] = fminf(colmin[jj], e + pp2[ii]);
                }
            }

            // per-warp column partials (pre-barrier stores)
#pragma unroll
            for (int jj = 0; jj < 4; jj++)
                cbuf[cur][ty][h * 64 + jj * 16 + tx] = colmin[jj];
        }

        // stage s+1 gt chunk -> other smem buffer (prefetch regs landed)
        if (s + 1 < NSTAGES && tid < TGQ)
            sg[nxt][tid] = make_float4(rx, ry, rz, rx * rx + ry * ry + rz * rz);

        __syncthreads();   // the ONLY barrier per stage

        // column reduce overlaps next stage's compute in the other warps
        if (tid < TGQ) {
            float v[16];
#pragma unroll
            for (int t = 0; t < 16; t++) v[t] = cbuf[cur][t][tid];
#pragma unroll
            for (int st = 8; st > 0; st >>= 1)
#pragma unroll
                for (int t = 0; t < 8; t++)
                    if (t < st) v[t] = fminf(v[t], v[t + st]);
            float m = fmaxf(v[0], EPSF);   // clamp (ref); positive bits
            // complement encoding: min(m) == max(0x7f7fffff - bits(m)); init 0 == FLT_MAX
            atomicMax(&g_colmax[b * NPT + s * TGQ + tid],
                      0x7f7fffffu - (unsigned int)__float_as_int(m));
        }
    }

    // row-min reduce across tx: lanes differing in low 4 bits share ty and
    // partition g columns -> xor-shuffle over 1,2,4,8 completes the min.
#pragma unroll
    for (int ii = 0; ii < 8; ii++) {
        float m = rowmin[ii];
#pragma unroll
        for (int off = 1; off < 16; off <<= 1)
            m = fminf(m, __shfl_xor_sync(0xffffffffu, m, off));
        rowmin[ii] = m;
    }

    float rsum = 0.f;
    if (tx == 0) {
#pragma unroll
        for (int ii = 0; ii < 8; ii++)
            rsum += sqrtf(fmaxf(rowmin[ii] + pp2[ii], EPSF));
    }

    sred[tid] = rsum;
    __syncthreads();
    for (int st = NTH / 2; st > 0; st >>= 1) {
        if (tid < st) sred[tid] += sred[tid + st];
        __syncthreads();
    }

    // ---- single-launch epilogue: fixed-point row add, then last block finalizes
    if (tid == 0) {
        unsigned long long fx =
            (unsigned long long)((double)sred[0] * FPSCALE + 0.5);
        atomicAdd(&g_rowacc, fx);          // integer add: commutative => deterministic
        __threadfence();                    // make colmax/rowacc visible before ticket
        ticket = atomicAdd(&g_done, 1u);
    }
    __syncthreads();

    if (ticket == NBLOCKS - 1) {
        // all other blocks have passed their fence: finalize + reset state
        float s = 0.f;
        for (int i = tid; i < BATCH * NPT; i += NTH) {
            unsigned int c = g_colmax[i];
            s += sqrtf(__int_as_float((int)(0x7f7fffffu - c)));  // clamped >= EPS already
            g_colmax[i] = 0u;                                    // reset for next replay
        }
        sred[tid] = s;
        __syncthreads();
        for (int st = NTH / 2; st > 0; st >>= 1) {
            if (tid < st) sred[tid] += sred[tid + st];
            __syncthreads();
        }
        if (tid == 0) {
            double total = (double)sred[0] + (double)g_rowacc / FPSCALE;
            out[0] = (float)(total / (double)(BATCH * 2 * NPT));  // denom = B*(Np+Ng)
            g_rowacc = 0ull;                                      // reset
            g_done   = 0u;                                        // reset
        }
    }
}

extern "C" void kernel_launch(void* const* d_in, const int* in_sizes, int n_in,
                              void* d_out, int out_size) {
    const float* P = (const float*)d_in[0];
    const float* G = (const float*)d_in[1];

    dim3 grid(NPT / TPQ, BATCH);             // 64 x 4 = 256 blocks, ONE launch
    chamfer_main<<<grid, NTH>>>(P, G, (float*)d_out);
}

// round 11
// speedup vs baseline: 1.5806x; 1.3345x over previous
#include <cuda_runtime.h>
#include <math.h>

// Chamfer loss, B=4, C=3, Np=Ng=8192. R11 = R10 single-launch design with a
// VECTORIZED last-block finalize (uint4 ldcg + unroll -> high MLP) replacing
// the serial scalar loop that cost ~33us in R10.
//  - col-min as atomicMax of (0x7f7fffff - bits): zero-init == FLT_MAX (no init kernel)
//  - row partials in fixed-point u64 (integer adds commute => deterministic)
//  - last block (ticket) finalizes and resets all globals for graph replay.

#define BATCH   4
#define NPT     8192
#define TPQ     128                      // predict points per block
#define TGQ     128                      // gt points per stage
#define NSTAGES (NPT / TGQ)              // 64
#define NTH     256                      // 16 (g=tx) x 16 (p=ty)
#define NBLOCKS (BATCH * (NPT / TPQ))    // 256
#define EPSF    1e-12f
#define FPSCALE 4294967296.0             // 2^32 fixed point

__device__ unsigned int       g_colmax[BATCH * NPT];   // complement-encoded mins (0 = FLT_MAX)
__device__ unsigned long long g_rowacc;                // fixed-point row-sum accumulator
__device__ unsigned int       g_done;                  // completed-block counter

__global__ __launch_bounds__(NTH, 3)
void chamfer_main(const float* __restrict__ P, const float* __restrict__ G,
                  float* __restrict__ out) {
    const int b     = blockIdx.y;
    const int pbase = blockIdx.x * TPQ;
    const float* Pb = P + (size_t)b * 3 * NPT;
    const float* Gb = G + (size_t)b * 3 * NPT;
    const int tid = threadIdx.x;
    const int tx  = tid & 15;        // g direction
    const int ty  = tid >> 4;        // p direction

    __shared__ float4 sp[TPQ];
    __shared__ float4 sg[2][TGQ];               // double buffer
    __shared__ float  cbuf[2][16][TGQ + 1];     // double buffer, padded
    __shared__ float  sred[NTH];
    __shared__ unsigned int ticket;

    // ---- prologue: prefetch stage-0 gt, load & transform p tile ----
    float rx = 0.f, ry = 0.f, rz = 0.f;
    if (tid < TGQ) {
        rx = Gb[tid];
        ry = Gb[NPT + tid];
        rz = Gb[2 * NPT + tid];
    }
    for (int i = tid; i < TPQ; i += NTH) {
        float px = Pb[pbase + i];
        float py = Pb[NPT + pbase + i];
        float pz = Pb[2 * NPT + pbase + i];
        sp[i] = make_float4(-2.f * px, -2.f * py, -2.f * pz,
                            px * px + py * py + pz * pz);
    }
    if (tid < TGQ)
        sg[0][tid] = make_float4(rx, ry, rz, rx * rx + ry * ry + rz * rz);
    __syncthreads();

    float pa[8], pb_[8], pc[8], pp2[8], rowmin[8];
#pragma unroll
    for (int ii = 0; ii < 8; ii++) {
        float4 v = sp[ty * 8 + ii];
        pa[ii] = v.x; pb_[ii] = v.y; pc[ii] = v.z; pp2[ii] = v.w;
        rowmin[ii] = 3.4e38f;
    }

    for (int s = 0; s < NSTAGES; s++) {
        const int cur = s & 1, nxt = cur ^ 1;

        // issue next-stage gmem loads now; latency hidden under compute
        if (s + 1 < NSTAGES && tid < TGQ) {
            int g = (s + 1) * TGQ + tid;
            rx = Gb[g]; ry = Gb[NPT + g]; rz = Gb[2 * NPT + g];
        }

        // two g-passes of 64 columns each (RG=4) to keep registers small
#pragma unroll
        for (int h = 0; h < 2; h++) {
            float gx[4], gy[4], gz[4], g2[4], colmin[4];
#pragma unroll
            for (int jj = 0; jj < 4; jj++) {
                float4 v = sg[cur][h * 64 + jj * 16 + tx];
                gx[jj] = v.x; gy[jj] = v.y; gz[jj] = v.z; g2[jj] = v.w;
                colmin[jj] = 3.4e38f;
            }

#pragma unroll
            for (int ii = 0; ii < 8; ii++) {
#pragma unroll
                for (int jj = 0; jj < 4; jj++) {
                    float e = fmaf(pc[ii], gz[jj], g2[jj]);
                    e = fmaf(pb_[ii], gy[jj], e);
                    e = fmaf(pa[ii], gx[jj], e);
                    rowmin[ii] = fminf(rowmin[ii], e);
                    colmin[jj] = fminf(colmin[jj], e + pp2[ii]);
                }
            }

            // per-warp column partials (pre-barrier stores)
#pragma unroll
            for (int jj = 0; jj < 4; jj++)
                cbuf[cur][ty][h * 64 + jj * 16 + tx] = colmin[jj];
        }

        // stage s+1 gt chunk -> other smem buffer (prefetch regs landed)
        if (s + 1 < NSTAGES && tid < TGQ)
            sg[nxt][tid] = make_float4(rx, ry, rz, rx * rx + ry * ry + rz * rz);

        __syncthreads();   // the ONLY barrier per stage

        // column reduce overlaps next stage's compute in the other warps
        if (tid < TGQ) {
            float v[16];
#pragma unroll
            for (int t = 0; t < 16; t++) v[t] = cbuf[cur][t][tid];
#pragma unroll
            for (int st = 8; st > 0; st >>= 1)
#pragma unroll
                for (int t = 0; t < 8; t++)
                    if (t < st) v[t] = fminf(v[t], v[t + st]);
            float m = fmaxf(v[0], EPSF);   // clamp (ref); positive bits
            // complement encoding: min(m) == max(0x7f7fffff - bits(m)); init 0 == FLT_MAX
            atomicMax(&g_colmax[b * NPT + s * TGQ + tid],
                      0x7f7fffffu - (unsigned int)__float_as_int(m));
        }
    }

    // row-min reduce across tx: lanes differing in low 4 bits share ty and
    // partition g columns -> xor-shuffle over 1,2,4,8 completes the min.
#pragma unroll
    for (int ii = 0; ii < 8; ii++) {
        float m = rowmin[ii];
#pragma unroll
        for (int off = 1; off < 16; off <<= 1)
            m = fminf(m, __shfl_xor_sync(0xffffffffu, m, off));
        rowmin[ii] = m;
    }

    float rsum = 0.f;
    if (tx == 0) {
#pragma unroll
        for (int ii = 0; ii < 8; ii++)
            rsum += sqrtf(fmaxf(rowmin[ii] + pp2[ii], EPSF));
    }

    sred[tid] = rsum;
    __syncthreads();
    for (int st = NTH / 2; st > 0; st >>= 1) {
        if (tid < st) sred[tid] += sred[tid + st];
        __syncthreads();
    }

    // ---- single-launch epilogue: fixed-point row add, then last block finalizes
    if (tid == 0) {
        unsigned long long fx =
            (unsigned long long)((double)sred[0] * FPSCALE + 0.5);
        atomicAdd(&g_rowacc, fx);          // integer add: commutative => deterministic
        __threadfence();                    // make colmax/rowacc visible before ticket
        ticket = atomicAdd(&g_done, 1u);
    }
    __syncthreads();

    if (ticket == NBLOCKS - 1) {
        // all other blocks have passed their fence. Vectorized gather + reset:
        // 8192 uint4 across 256 threads = 32 wide loads/thread (high MLP).
        uint4* cm4 = reinterpret_cast<uint4*>(g_colmax);
        const uint4 z4 = make_uint4(0u, 0u, 0u, 0u);
        float s = 0.f;
#pragma unroll 4
        for (int i = tid; i < (BATCH * NPT) / 4; i += NTH) {
            uint4 c = __ldcg(&cm4[i]);
            s += sqrtf(__int_as_float((int)(0x7f7fffffu - c.x)));
            s += sqrtf(__int_as_float((int)(0x7f7fffffu - c.y)));
            s += sqrtf(__int_as_float((int)(0x7f7fffffu - c.z)));
            s += sqrtf(__int_as_float((int)(0x7f7fffffu - c.w)));
            cm4[i] = z4;                                         // reset for next replay
        }
        sred[tid] = s;
        __syncthreads();
        for (int st = NTH / 2; st > 0; st >>= 1) {
            if (tid < st) sred[tid] += sred[tid + st];
            __syncthreads();
        }
        if (tid == 0) {
            double total = (double)sred[0] + (double)g_rowacc / FPSCALE;
            out[0] = (float)(total / (double)(BATCH * 2 * NPT));  // denom = B*(Np+Ng)
            g_rowacc = 0ull;                                      // reset
            g_done   = 0u;                                        // reset
        }
    }
}

extern "C" void kernel_launch(void* const* d_in, const int* in_sizes, int n_in,
                              void* d_out, int out_size) {
    const float* P = (const float*)d_in[0];
    const float* G = (const float*)d_in[1];

    dim3 grid(NPT / TPQ, BATCH);             // 64 x 4 = 256 blocks, ONE launch
    chamfer_main<<<grid, NTH>>>(P, G, (float*)d_out);
}